// round 16
// baseline (speedup 1.0000x reference)
#include <cuda_runtime.h>
#include <cuda_fp16.h>
#include <stdint.h>

#define T_  128
#define B_  1024
#define D_  96
#define H_  128
#define BH  (B_ * H_)      // 131072
#define NSL 129

#define BETA   0.9f
#define THRESH 0.5f

// C[t] = x_t @ W_in^T stored at slice t+1 (slice 0 unused)
__device__ float g_P[(size_t)NSL * BH];           // ~67.6 MB
// layer-1 spikes as bits: [t][s][b][4 words of 32 h-bits]
__device__ uint16_t g_S[(size_t)T_ * 7 * B_ * 8]; // 14.7 MB

#define SPK_STR   272
#define SPK_BYTES 17408
#define W_BYTES   (128 * SPK_STR)
// precomputed fp16 2-term split of Wh0, exact smem image (2 terms)
__device__ __align__(16) uint8_t g_Wh16[2 * W_BYTES];

__device__ __forceinline__ uint32_t pack_half2(__half lo, __half hi) {
    return (uint32_t)__half_as_ushort(lo) | ((uint32_t)__half_as_ushort(hi) << 16);
}

// ---------------------------------------------------------------------------
// Kernel 1: C = X @ W_in^T  (at FFMA roofline; unchanged)
// ---------------------------------------------------------------------------
__global__ void __launch_bounds__(512, 2)
k_gemm_in(const float* __restrict__ x, const float* __restrict__ Win) {
    extern __shared__ float sm[];
    float* Ws  = sm;                 // [96][132]
    float* At  = sm + 96 * 132;      // [96][132]
    const int tid  = threadIdx.x;
    const int row0 = blockIdx.x * 128;

    for (int idx = tid; idx < H_ * D_; idx += 512) {
        int h = idx / D_, k = idx - h * D_;
        Ws[k * 132 + h] = Win[idx];
    }
    for (int idx = tid; idx < 128 * D_; idx += 512) {
        int r = idx / D_, k = idx - r * D_;
        At[k * 132 + r] = x[(size_t)row0 * D_ + idx];
    }
    __syncthreads();

    const int tx = tid & 31, ty = tid >> 5;
    const int r0 = ty * 8;
    const int c0 = tx * 4;
    float acc[8][4] = {};
    #pragma unroll 2
    for (int k = 0; k < D_; ++k) {
        const float4 w  = *(const float4*)(Ws + k * 132 + c0);
        const float4 aA = *(const float4*)(At + k * 132 + r0);
        const float4 aB = *(const float4*)(At + k * 132 + r0 + 4);
        const float av[8] = {aA.x, aA.y, aA.z, aA.w, aB.x, aB.y, aB.z, aB.w};
        #pragma unroll
        for (int i = 0; i < 8; ++i) {
            acc[i][0] = fmaf(av[i], w.x, acc[i][0]);
            acc[i][1] = fmaf(av[i], w.y, acc[i][1]);
            acc[i][2] = fmaf(av[i], w.z, acc[i][2]);
            acc[i][3] = fmaf(av[i], w.w, acc[i][3]);
        }
    }
    #pragma unroll
    for (int i = 0; i < 8; ++i)
        *(float4*)(g_P + (size_t)BH + (size_t)(row0 + r0 + i) * H_ + c0) =
            make_float4(acc[i][0], acc[i][1], acc[i][2], acc[i][3]);
}

// ---------------------------------------------------------------------------
// Kernel 1b: one-shot fp16 2-term split of Wh0 into the exact smem image
// ---------------------------------------------------------------------------
__global__ void k_wsplit(const float* __restrict__ Wh0) {
    const int idx = blockIdx.x * 256 + threadIdx.x;   // 0..8191 (float2 units)
    const float2 wv = ((const float2*)Wh0)[idx];
    const int n = idx >> 6, k2 = idx & 63;
    __half hx1 = __float2half_rn(wv.x);
    __half hx2 = __float2half_rn(wv.x - __half2float(hx1));
    __half hy1 = __float2half_rn(wv.y);
    __half hy2 = __float2half_rn(wv.y - __half2float(hy1));
    const int off = n * SPK_STR + k2 * 4;
    *(__half2*)(g_Wh16 + 0 * W_BYTES + off) = __halves2half2(hx2, hy2);
    *(__half2*)(g_Wh16 + 1 * W_BYTES + off) = __halves2half2(hx1, hy1);
}

// ---------------------------------------------------------------------------
// Kernel 2: fused prefix + layer-1.  Phase 1 MLP=8; Phase 2 4-way t-interleave.
// All float arithmetic bit-identical to R15.
// ---------------------------------------------------------------------------
__device__ __forceinline__ void wbounds(int t, int s, int& lo, int& hi) {
    if (t >= 49) { lo = t - 49 + 7 * s; hi = lo + 7; }
    else {
        int j0 = 7 * s; if (j0 < 1) j0 = 1;
        int j1 = 7 * s + 6; if (j1 > t + 1) j1 = t + 1;
        lo = j0 - 1;
        hi = (j1 >= j0) ? j1 : lo;
    }
}

__global__ void __launch_bounds__(128)
k_pl1() {
    extern __shared__ float ring[];               // [129][128]
    const int tid  = threadIdx.x;
    const int g    = blockIdx.x * 128 + tid;
    const int b    = g >> 7;
    const int hw   = (g & 127) >> 5;
    const int lane = tid & 31;
    uint32_t* Sp = (uint32_t*)g_S;

    // ---- Phase 1: full prefix, 8-deep LDG pipeline (order-identical) ----
    float run = 0.f;
    ring[tid] = 0.f;
    float cb[8];
    #pragma unroll
    for (int i = 0; i < 8; ++i)
        cb[i] = g_P[(size_t)(1 + i) * BH + g];
    for (int t = 0; t < T_; ++t) {
        run += cb[t & 7];
        if (t + 8 < T_) cb[t & 7] = g_P[(size_t)(t + 9) * BH + g];
        ring[(t + 1) * 128 + tid] = run;
    }

    // ---- Phase 2: four independent t-chains per iteration ----
    for (int t = 0; t < T_; t += 4) {
        float m1[4] = {0.f, 0.f, 0.f, 0.f};
        size_t outB[4];
        #pragma unroll
        for (int q = 0; q < 4; ++q)
            outB[q] = (((size_t)(t + q) * 7) * B_ + b) * 4 + hw;
        #pragma unroll
        for (int s = 0; s < 7; ++s) {
            uint32_t bal[4];
            #pragma unroll
            for (int q = 0; q < 4; ++q) {
                int lo, hi;
                wbounds(t + q, s, lo, hi);
                float cur = ring[hi * 128 + tid] - ring[lo * 128 + tid];
                float m = m1[q];
                m1[q] = (m > THRESH) ? 0.f : fmaf(BETA, m, cur);
                bal[q] = __ballot_sync(0xffffffffu, m1[q] > THRESH);
            }
            if (lane == 0) {
                #pragma unroll
                for (int q = 0; q < 4; ++q)
                    Sp[outB[q] + (size_t)s * B_ * 4] = bal[q];
            }
        }
    }
}

// ---------------------------------------------------------------------------
// Kernel 3: hidden GEMM + layer 2 + output (unchanged from R15)
// ---------------------------------------------------------------------------
#define SM_SPK0   0
#define SM_SPK1   17408
#define SM_W      34816
#define SM_MOUT   104448                 // 512
#define SM_SRED   104960                 // 2 x 2048
#define SM_TOTAL  109056

__device__ __forceinline__ uint32_t s2u(const void* p) {
    uint32_t a;
    asm("{ .reg .u64 t; cvta.to.shared.u64 t, %1; cvt.u32.u64 %0, t; }"
        : "=r"(a) : "l"(p));
    return a;
}

__device__ __forceinline__ void ldm4(uint32_t* r, uint32_t addr) {
    asm volatile("ldmatrix.sync.aligned.m8n8.x4.shared.b16 {%0,%1,%2,%3}, [%4];"
        : "=r"(r[0]), "=r"(r[1]), "=r"(r[2]), "=r"(r[3]) : "r"(addr));
}

__device__ __forceinline__ void mma16816(float* d, const uint32_t* a,
                                         uint32_t b0, uint32_t b1) {
    asm("mma.sync.aligned.m16n8k16.row.col.f32.f16.f16.f32 "
        "{%0,%1,%2,%3}, {%4,%5,%6,%7}, {%8,%9}, {%0,%1,%2,%3};"
        : "+f"(d[0]), "+f"(d[1]), "+f"(d[2]), "+f"(d[3])
        : "r"(a[0]), "r"(a[1]), "r"(a[2]), "r"(a[3]), "r"(b0), "r"(b1));
}

__global__ void __launch_bounds__(256, 2)
k_snn_b(const float* __restrict__ Wout,
        const float* __restrict__ vx, const float* __restrict__ vy,
        float* __restrict__ out)
{
    extern __shared__ char smc[];
    const uint32_t smb = s2u(smc);
    float* memout = (float*)(smc + SM_MOUT);

    const int tid  = threadIdx.x;
    const int w    = tid >> 5;
    const int lane = tid & 31;
    const int mg   = w & 1;
    const int ng   = w >> 1;
    const int t    = blockIdx.x >> 4;
    const int b0   = (blockIdx.x & 15) << 6;

    // ---- copy precomputed W image (2 terms, 69632 B) ----
    {
        const uint4* src = (const uint4*)g_Wh16;
        uint4* dst = (uint4*)(smc + SM_W);
        #pragma unroll
        for (int i = 0; i < 17; ++i)
            dst[i * 256 + tid] = src[i * 256 + tid];
    }
    if (tid < 128) memout[tid] = 0.f;

    // ---- per-warp Wout B-fragments (2-term fp16 split), built once ----
    uint32_t bW[2][2][2];
    {
        const int n   = lane >> 2;
        const int tig = lane & 3;
        #pragma unroll
        for (int kt = 0; kt < 2; ++kt) {
            #pragma unroll
            for (int j = 0; j < 2; ++j) {
                const int k0 = 32 * ng + 16 * kt + 2 * tig + 8 * j;
                float w0 = (n < 2) ? Wout[n * 128 + k0]     : 0.f;
                float w1 = (n < 2) ? Wout[n * 128 + k0 + 1] : 0.f;
                __half h0 = __float2half_rn(w0);
                __half l0 = __float2half_rn(w0 - __half2float(h0));
                __half h1 = __float2half_rn(w1);
                __half l1 = __float2half_rn(w1 - __half2float(h1));
                bW[1][kt][j] = pack_half2(h0, h1);
                bW[0][kt][j] = pack_half2(l0, l1);
            }
        }
    }

    // ---- prefetch all 7 spike words ----
    const int wq = tid >> 6;
    const int re = tid & 63;
    uint32_t spw[7];
    {
        const uint32_t* Sp = (const uint32_t*)g_S;
        #pragma unroll
        for (int s = 0; s < 7; ++s)
            spw[s] = Sp[(((size_t)t * 7 + s) * B_ + b0 + re) * 4 + wq];
    }

    float mem2[2][4][4];
    #pragma unroll
    for (int mt = 0; mt < 2; ++mt)
        #pragma unroll
        for (int nt = 0; nt < 4; ++nt)
            #pragma unroll
            for (int e = 0; e < 4; ++e) mem2[mt][nt][e] = 0.f;

    const int r00 = 32 * mg + (lane >> 2);
    const uint32_t aLd0 = smb + SM_SPK0 + (32 * mg + (lane & 15)) * SPK_STR
                        + ((lane >> 4) << 4);
    const uint32_t bLdBase = smb + SM_W + (32 * ng + (lane & 15)) * SPK_STR
                           + ((lane >> 4) << 4);
    const uint32_t expDst0 = smb + SM_SPK0 + re * SPK_STR + wq * 64;

    // ---- expand step 0 into buffer 0 ----
    {
        const uint32_t bits = spw[0];
        uint32_t hv[16];
        #pragma unroll
        for (int j = 0; j < 16; ++j)
            hv[j] = ((bits >> (2*j)) & 1u ? 0x3C00u : 0u)
                  | ((bits >> (2*j+1)) & 1u ? 0x3C000000u : 0u);
        #pragma unroll
        for (int q = 0; q < 4; ++q)
            *(uint4*)(smc + SM_SPK0 + re * SPK_STR + wq * 64 + 16 * q) =
                make_uint4(hv[4*q], hv[4*q+1], hv[4*q+2], hv[4*q+3]);
    }
    __syncthreads();

    for (int s = 0; s < 7; ++s) {
        const uint32_t aLdBase = aLd0 + (uint32_t)(s & 1) * SPK_BYTES;

        float acc[2][4][4];
        #pragma unroll
        for (int mt = 0; mt < 2; ++mt)
            #pragma unroll
            for (int nt = 0; nt < 4; ++nt)
                #pragma unroll
                for (int e = 0; e < 4; ++e) acc[mt][nt][e] = 0.f;

        // ---- hidden GEMM: acc = spk @ (Wlo + Whi)^T ----
        #pragma unroll
        for (int ks = 0; ks < 8; ++ks) {
            uint32_t a[2][4];
            #pragma unroll
            for (int mt = 0; mt < 2; ++mt)
                ldm4(a[mt], aLdBase + mt * (16 * SPK_STR) + ks * 32);
            #pragma unroll
            for (int term = 0; term < 2; ++term) {
                uint32_t b0r[4], b1r[4];
                ldm4(b0r, bLdBase + term * W_BYTES + ks * 32);
                ldm4(b1r, bLdBase + term * W_BYTES + 16 * SPK_STR + ks * 32);
                #pragma unroll
                for (int mt = 0; mt < 2; ++mt) {
                    mma16816(acc[mt][0], a[mt], b0r[0], b0r[2]);
                    mma16816(acc[mt][1], a[mt], b0r[1], b0r[3]);
                    mma16816(acc[mt][2], a[mt], b1r[0], b1r[2]);
                    mma16816(acc[mt][3], a[mt], b1r[1], b1r[3]);
                }
            }
        }

        // ---- expand step s+1 into the other buffer ----
        if (s < 6) {
            const uint32_t bits = spw[s + 1];
            uint32_t hv[16];
            #pragma unroll
            for (int j = 0; j < 16; ++j)
                hv[j] = ((bits >> (2*j)) & 1u ? 0x3C00u : 0u)
                      | ((bits >> (2*j+1)) & 1u ? 0x3C000000u : 0u);
            char* dstp = smc + (expDst0 - smb) + ((s + 1) & 1) * SPK_BYTES;
            #pragma unroll
            for (int q = 0; q < 4; ++q)
                *(uint4*)(dstp + 16 * q) = make_uint4(hv[4*q], hv[4*q+1],
                                                      hv[4*q+2], hv[4*q+3]);
        }

        // ---- layer 2: mem2 recurrence + pack spikes as A-fragments ----
        uint32_t aF[2][2][4];
        #pragma unroll
        for (int mt = 0; mt < 2; ++mt)
            #pragma unroll
            for (int nt = 0; nt < 4; ++nt) {
                float nm[4];
                #pragma unroll
                for (int e = 0; e < 4; ++e) {
                    float m = mem2[mt][nt][e];
                    nm[e] = (m > THRESH) ? 0.f : fmaf(BETA, m, acc[mt][nt][e]);
                    mem2[mt][nt][e] = nm[e];
                }
                uint32_t lo = (nm[0] > THRESH ? 0x3C00u : 0u)
                            | (nm[1] > THRESH ? 0x3C000000u : 0u);
                uint32_t hi = (nm[2] > THRESH ? 0x3C00u : 0u)
                            | (nm[3] > THRESH ? 0x3C000000u : 0u);
                const int kt = nt >> 1;
                const int oj = (nt & 1) ? 2 : 0;
                aF[mt][kt][oj]     = lo;
                aF[mt][kt][oj + 1] = hi;
            }

        // ---- projection via MMA ----
        float pacc[2][4];
        #pragma unroll
        for (int mt = 0; mt < 2; ++mt)
            #pragma unroll
            for (int e = 0; e < 4; ++e) pacc[mt][e] = 0.f;
        #pragma unroll
        for (int term = 0; term < 2; ++term)
            #pragma unroll
            for (int kt = 0; kt < 2; ++kt)
                #pragma unroll
                for (int mt = 0; mt < 2; ++mt)
                    mma16816(pacc[mt], aF[mt][kt],
                             bW[term][kt][0], bW[term][kt][1]);

        char* sredBuf = smc + SM_SRED + (s & 1) * 2048;
        if ((lane & 3) == 0) {
            #pragma unroll
            for (int mt = 0; mt < 2; ++mt) {
                const int row = r00 + 16 * mt;
                *(float*)(sredBuf + (((row    ) * 2 + 0) * 4 + ng) * 4) = pacc[mt][0];
                *(float*)(sredBuf + (((row    ) * 2 + 1) * 4 + ng) * 4) = pacc[mt][1];
                *(float*)(sredBuf + (((row + 8) * 2 + 0) * 4 + ng) * 4) = pacc[mt][2];
                *(float*)(sredBuf + (((row + 8) * 2 + 1) * 4 + ng) * 4) = pacc[mt][3];
            }
        }
        __syncthreads();

        if (tid < 128) {
            const float4 v = *(const float4*)(sredBuf + tid * 16);
            float sum = (v.x + v.y) + (v.z + v.w);
            memout[tid] = fmaf(BETA, memout[tid], sum);
        }
    }

    // ---- epilogue ----
    if (tid < 128) {
        const int row = tid >> 1, o = tid & 1;
        const float v = o ? vy[0] : vx[0];
        out[((size_t)t * B_ + b0 + row) * 2 + o] = memout[tid] * v;
    }
}

// ---------------------------------------------------------------------------
extern "C" void kernel_launch(void* const* d_in, const int* in_sizes, int n_in,
                              void* d_out, int out_size) {
    const float* x    = (const float*)d_in[0];
    const float* Win  = (const float*)d_in[1];
    const float* Wh0  = (const float*)d_in[2];
    const float* Wout = (const float*)d_in[3];
    const float* vx   = (const float*)d_in[4];
    const float* vy   = (const float*)d_in[5];
    float* out = (float*)d_out;

    const int smem1 = (96 * 132 + 96 * 132) * 4;   // 101376 B
    const int smem2 = 129 * 128 * 4;               // 66048 B
    cudaFuncSetAttribute(k_gemm_in, cudaFuncAttributeMaxDynamicSharedMemorySize, smem1);
    cudaFuncSetAttribute(k_pl1,     cudaFuncAttributeMaxDynamicSharedMemorySize, smem2);
    cudaFuncSetAttribute(k_snn_b,   cudaFuncAttributeMaxDynamicSharedMemorySize, SM_TOTAL);

    k_gemm_in<<<(T_ * B_) / 128, 512, smem1>>>(x, Win);
    k_wsplit<<<32, 256>>>(Wh0);
    k_pl1<<<BH / 128, 128, smem2>>>();
    k_snn_b<<<T_ * 16, 256, SM_TOTAL>>>(Wout, vx, vy, out);
}

// round 17
// speedup vs baseline: 1.0401x; 1.0401x over previous
#include <cuda_runtime.h>
#include <cuda_fp16.h>
#include <stdint.h>

#define T_  128
#define B_  1024
#define D_  96
#define H_  128
#define BH  (B_ * H_)      // 131072
#define NSL 129

#define BETA   0.9f
#define THRESH 0.5f

// C[t] = x_t @ W_in^T stored at slice t+1 (slice 0 unused)
__device__ float g_P[(size_t)NSL * BH];           // ~67.6 MB
// layer-1 spikes as bits: [t][s][b][4 words of 32 h-bits]
__device__ uint16_t g_S[(size_t)T_ * 7 * B_ * 8]; // 14.7 MB

#define SPK_STR   272
#define SPK_BYTES 17408
#define W_BYTES   (128 * SPK_STR)
// precomputed fp16 2-term split of Wh0, exact smem image (2 terms)
__device__ __align__(16) uint8_t g_Wh16[2 * W_BYTES];

__device__ __forceinline__ uint32_t pack_half2(__half lo, __half hi) {
    return (uint32_t)__half_as_ushort(lo) | ((uint32_t)__half_as_ushort(hi) << 16);
}

// ---------------------------------------------------------------------------
// Kernel 1: C = X @ W_in^T  (FFMA roofline).  Block 1024 additionally does
// the one-shot fp16 2-term Wh0 split (independent work, overlapped).
// ---------------------------------------------------------------------------
__global__ void __launch_bounds__(512, 2)
k_gemm_in(const float* __restrict__ x, const float* __restrict__ Win,
          const float* __restrict__ Wh0) {
    extern __shared__ float sm[];
    const int tid = threadIdx.x;

    if (blockIdx.x == 1024) {
        // ---- Wh0 split: 8192 float2 elements over 512 threads ----
        const float2* W2 = (const float2*)Wh0;
        #pragma unroll
        for (int i = 0; i < 16; ++i) {
            const int idx = i * 512 + tid;
            const float2 wv = W2[idx];
            const int n = idx >> 6, k2 = idx & 63;
            __half hx1 = __float2half_rn(wv.x);
            __half hx2 = __float2half_rn(wv.x - __half2float(hx1));
            __half hy1 = __float2half_rn(wv.y);
            __half hy2 = __float2half_rn(wv.y - __half2float(hy1));
            const int off = n * SPK_STR + k2 * 4;
            *(__half2*)(g_Wh16 + 0 * W_BYTES + off) = __halves2half2(hx2, hy2);
            *(__half2*)(g_Wh16 + 1 * W_BYTES + off) = __halves2half2(hx1, hy1);
        }
        return;
    }

    float* Ws  = sm;                 // [96][132]
    float* At  = sm + 96 * 132;      // [96][132]
    const int row0 = blockIdx.x * 128;

    for (int idx = tid; idx < H_ * D_; idx += 512) {
        int h = idx / D_, k = idx - h * D_;
        Ws[k * 132 + h] = Win[idx];
    }
    for (int idx = tid; idx < 128 * D_; idx += 512) {
        int r = idx / D_, k = idx - r * D_;
        At[k * 132 + r] = x[(size_t)row0 * D_ + idx];
    }
    __syncthreads();

    const int tx = tid & 31, ty = tid >> 5;
    const int r0 = ty * 8;
    const int c0 = tx * 4;
    float acc[8][4] = {};
    #pragma unroll 2
    for (int k = 0; k < D_; ++k) {
        const float4 w  = *(const float4*)(Ws + k * 132 + c0);
        const float4 aA = *(const float4*)(At + k * 132 + r0);
        const float4 aB = *(const float4*)(At + k * 132 + r0 + 4);
        const float av[8] = {aA.x, aA.y, aA.z, aA.w, aB.x, aB.y, aB.z, aB.w};
        #pragma unroll
        for (int i = 0; i < 8; ++i) {
            acc[i][0] = fmaf(av[i], w.x, acc[i][0]);
            acc[i][1] = fmaf(av[i], w.y, acc[i][1]);
            acc[i][2] = fmaf(av[i], w.z, acc[i][2]);
            acc[i][3] = fmaf(av[i], w.w, acc[i][3]);
        }
    }
    #pragma unroll
    for (int i = 0; i < 8; ++i)
        *(float4*)(g_P + (size_t)BH + (size_t)(row0 + r0 + i) * H_ + c0) =
            make_float4(acc[i][0], acc[i][1], acc[i][2], acc[i][3]);
}

// ---------------------------------------------------------------------------
// Kernel 2: fused prefix + layer-1.  Phase 1: MLP=8 with explicit unroll-8
// (static cb indices -> guaranteed register residency).  Phase 2: exact
// R15 2-way t-interleave.  All float arithmetic bit-identical.
// ---------------------------------------------------------------------------
__global__ void __launch_bounds__(128)
k_pl1() {
    extern __shared__ float ring[];               // [129][128]
    const int tid  = threadIdx.x;
    const int g    = blockIdx.x * 128 + tid;
    const int b    = g >> 7;
    const int hw   = (g & 127) >> 5;
    const int lane = tid & 31;
    uint32_t* Sp = (uint32_t*)g_S;

    // ---- Phase 1: full prefix, 8-deep LDG pipeline, forced unroll ----
    float run = 0.f;
    ring[tid] = 0.f;
    float cb[8];
    #pragma unroll
    for (int i = 0; i < 8; ++i)
        cb[i] = g_P[(size_t)(1 + i) * BH + g];
    #pragma unroll 8
    for (int t = 0; t < T_; ++t) {
        run += cb[t & 7];
        if (t + 8 < T_) cb[t & 7] = g_P[(size_t)(t + 9) * BH + g];
        ring[(t + 1) * 128 + tid] = run;
    }

    // ---- Phase 2: two independent t-chains per iteration (R15 form) ----
    for (int t = 0; t < T_; t += 2) {
        const int ta = t, tb = t + 1;
        float m1a = 0.f, m1b = 0.f;
        const size_t outA = (((size_t)ta * 7) * B_ + b) * 4 + hw;
        const size_t outB = (((size_t)tb * 7) * B_ + b) * 4 + hw;
        #pragma unroll
        for (int s = 0; s < 7; ++s) {
            int loa, hia, lob, hib;
            if (ta >= 49) { loa = ta - 49 + 7 * s; hia = loa + 7; }
            else {
                int j0 = 7 * s; if (j0 < 1) j0 = 1;
                int j1 = 7 * s + 6; if (j1 > ta + 1) j1 = ta + 1;
                loa = j0 - 1;
                hia = (j1 >= j0) ? j1 : loa;
            }
            if (tb >= 49) { lob = tb - 49 + 7 * s; hib = lob + 7; }
            else {
                int j0 = 7 * s; if (j0 < 1) j0 = 1;
                int j1 = 7 * s + 6; if (j1 > tb + 1) j1 = tb + 1;
                lob = j0 - 1;
                hib = (j1 >= j0) ? j1 : lob;
            }
            float cura = ring[hia * 128 + tid] - ring[loa * 128 + tid];
            float curb = ring[hib * 128 + tid] - ring[lob * 128 + tid];
            m1a = (m1a > THRESH) ? 0.f : fmaf(BETA, m1a, cura);
            m1b = (m1b > THRESH) ? 0.f : fmaf(BETA, m1b, curb);
            uint32_t ba = __ballot_sync(0xffffffffu, m1a > THRESH);
            uint32_t bb = __ballot_sync(0xffffffffu, m1b > THRESH);
            if (lane == 0) {
                Sp[outA + (size_t)s * B_ * 4] = ba;
                Sp[outB + (size_t)s * B_ * 4] = bb;
            }
        }
    }
}

// ---------------------------------------------------------------------------
// Kernel 3: hidden GEMM + layer 2 + output (unchanged from R15)
// ---------------------------------------------------------------------------
#define SM_SPK0   0
#define SM_SPK1   17408
#define SM_W      34816
#define SM_MOUT   104448                 // 512
#define SM_SRED   104960                 // 2 x 2048
#define SM_TOTAL  109056

__device__ __forceinline__ uint32_t s2u(const void* p) {
    uint32_t a;
    asm("{ .reg .u64 t; cvta.to.shared.u64 t, %1; cvt.u32.u64 %0, t; }"
        : "=r"(a) : "l"(p));
    return a;
}

__device__ __forceinline__ void ldm4(uint32_t* r, uint32_t addr) {
    asm volatile("ldmatrix.sync.aligned.m8n8.x4.shared.b16 {%0,%1,%2,%3}, [%4];"
        : "=r"(r[0]), "=r"(r[1]), "=r"(r[2]), "=r"(r[3]) : "r"(addr));
}

__device__ __forceinline__ void mma16816(float* d, const uint32_t* a,
                                         uint32_t b0, uint32_t b1) {
    asm("mma.sync.aligned.m16n8k16.row.col.f32.f16.f16.f32 "
        "{%0,%1,%2,%3}, {%4,%5,%6,%7}, {%8,%9}, {%0,%1,%2,%3};"
        : "+f"(d[0]), "+f"(d[1]), "+f"(d[2]), "+f"(d[3])
        : "r"(a[0]), "r"(a[1]), "r"(a[2]), "r"(a[3]), "r"(b0), "r"(b1));
}

__global__ void __launch_bounds__(256, 2)
k_snn_b(const float* __restrict__ Wout,
        const float* __restrict__ vx, const float* __restrict__ vy,
        float* __restrict__ out)
{
    extern __shared__ char smc[];
    const uint32_t smb = s2u(smc);
    float* memout = (float*)(smc + SM_MOUT);

    const int tid  = threadIdx.x;
    const int w    = tid >> 5;
    const int lane = tid & 31;
    const int mg   = w & 1;
    const int ng   = w >> 1;
    const int t    = blockIdx.x >> 4;
    const int b0   = (blockIdx.x & 15) << 6;

    // ---- copy precomputed W image (2 terms, 69632 B) ----
    {
        const uint4* src = (const uint4*)g_Wh16;
        uint4* dst = (uint4*)(smc + SM_W);
        #pragma unroll
        for (int i = 0; i < 17; ++i)
            dst[i * 256 + tid] = src[i * 256 + tid];
    }
    if (tid < 128) memout[tid] = 0.f;

    // ---- per-warp Wout B-fragments (2-term fp16 split), built once ----
    uint32_t bW[2][2][2];
    {
        const int n   = lane >> 2;
        const int tig = lane & 3;
        #pragma unroll
        for (int kt = 0; kt < 2; ++kt) {
            #pragma unroll
            for (int j = 0; j < 2; ++j) {
                const int k0 = 32 * ng + 16 * kt + 2 * tig + 8 * j;
                float w0 = (n < 2) ? Wout[n * 128 + k0]     : 0.f;
                float w1 = (n < 2) ? Wout[n * 128 + k0 + 1] : 0.f;
                __half h0 = __float2half_rn(w0);
                __half l0 = __float2half_rn(w0 - __half2float(h0));
                __half h1 = __float2half_rn(w1);
                __half l1 = __float2half_rn(w1 - __half2float(h1));
                bW[1][kt][j] = pack_half2(h0, h1);
                bW[0][kt][j] = pack_half2(l0, l1);
            }
        }
    }

    // ---- prefetch all 7 spike words ----
    const int wq = tid >> 6;
    const int re = tid & 63;
    uint32_t spw[7];
    {
        const uint32_t* Sp = (const uint32_t*)g_S;
        #pragma unroll
        for (int s = 0; s < 7; ++s)
            spw[s] = Sp[(((size_t)t * 7 + s) * B_ + b0 + re) * 4 + wq];
    }

    float mem2[2][4][4];
    #pragma unroll
    for (int mt = 0; mt < 2; ++mt)
        #pragma unroll
        for (int nt = 0; nt < 4; ++nt)
            #pragma unroll
            for (int e = 0; e < 4; ++e) mem2[mt][nt][e] = 0.f;

    const int r00 = 32 * mg + (lane >> 2);
    const uint32_t aLd0 = smb + SM_SPK0 + (32 * mg + (lane & 15)) * SPK_STR
                        + ((lane >> 4) << 4);
    const uint32_t bLdBase = smb + SM_W + (32 * ng + (lane & 15)) * SPK_STR
                           + ((lane >> 4) << 4);
    const uint32_t expDst0 = smb + SM_SPK0 + re * SPK_STR + wq * 64;

    // ---- expand step 0 into buffer 0 ----
    {
        const uint32_t bits = spw[0];
        uint32_t hv[16];
        #pragma unroll
        for (int j = 0; j < 16; ++j)
            hv[j] = ((bits >> (2*j)) & 1u ? 0x3C00u : 0u)
                  | ((bits >> (2*j+1)) & 1u ? 0x3C000000u : 0u);
        #pragma unroll
        for (int q = 0; q < 4; ++q)
            *(uint4*)(smc + SM_SPK0 + re * SPK_STR + wq * 64 + 16 * q) =
                make_uint4(hv[4*q], hv[4*q+1], hv[4*q+2], hv[4*q+3]);
    }
    __syncthreads();

    for (int s = 0; s < 7; ++s) {
        const uint32_t aLdBase = aLd0 + (uint32_t)(s & 1) * SPK_BYTES;

        float acc[2][4][4];
        #pragma unroll
        for (int mt = 0; mt < 2; ++mt)
            #pragma unroll
            for (int nt = 0; nt < 4; ++nt)
                #pragma unroll
                for (int e = 0; e < 4; ++e) acc[mt][nt][e] = 0.f;

        // ---- hidden GEMM: acc = spk @ (Wlo + Whi)^T ----
        #pragma unroll
        for (int ks = 0; ks < 8; ++ks) {
            uint32_t a[2][4];
            #pragma unroll
            for (int mt = 0; mt < 2; ++mt)
                ldm4(a[mt], aLdBase + mt * (16 * SPK_STR) + ks * 32);
            #pragma unroll
            for (int term = 0; term < 2; ++term) {
                uint32_t b0r[4], b1r[4];
                ldm4(b0r, bLdBase + term * W_BYTES + ks * 32);
                ldm4(b1r, bLdBase + term * W_BYTES + 16 * SPK_STR + ks * 32);
                #pragma unroll
                for (int mt = 0; mt < 2; ++mt) {
                    mma16816(acc[mt][0], a[mt], b0r[0], b0r[2]);
                    mma16816(acc[mt][1], a[mt], b0r[1], b0r[3]);
                    mma16816(acc[mt][2], a[mt], b1r[0], b1r[2]);
                    mma16816(acc[mt][3], a[mt], b1r[1], b1r[3]);
                }
            }
        }

        // ---- expand step s+1 into the other buffer ----
        if (s < 6) {
            const uint32_t bits = spw[s + 1];
            uint32_t hv[16];
            #pragma unroll
            for (int j = 0; j < 16; ++j)
                hv[j] = ((bits >> (2*j)) & 1u ? 0x3C00u : 0u)
                      | ((bits >> (2*j+1)) & 1u ? 0x3C000000u : 0u);
            char* dstp = smc + (expDst0 - smb) + ((s + 1) & 1) * SPK_BYTES;
            #pragma unroll
            for (int q = 0; q < 4; ++q)
                *(uint4*)(dstp + 16 * q) = make_uint4(hv[4*q], hv[4*q+1],
                                                      hv[4*q+2], hv[4*q+3]);
        }

        // ---- layer 2: mem2 recurrence + pack spikes as A-fragments ----
        uint32_t aF[2][2][4];
        #pragma unroll
        for (int mt = 0; mt < 2; ++mt)
            #pragma unroll
            for (int nt = 0; nt < 4; ++nt) {
                float nm[4];
                #pragma unroll
                for (int e = 0; e < 4; ++e) {
                    float m = mem2[mt][nt][e];
                    nm[e] = (m > THRESH) ? 0.f : fmaf(BETA, m, acc[mt][nt][e]);
                    mem2[mt][nt][e] = nm[e];
                }
                uint32_t lo = (nm[0] > THRESH ? 0x3C00u : 0u)
                            | (nm[1] > THRESH ? 0x3C000000u : 0u);
                uint32_t hi = (nm[2] > THRESH ? 0x3C00u : 0u)
                            | (nm[3] > THRESH ? 0x3C000000u : 0u);
                const int kt = nt >> 1;
                const int oj = (nt & 1) ? 2 : 0;
                aF[mt][kt][oj]     = lo;
                aF[mt][kt][oj + 1] = hi;
            }

        // ---- projection via MMA ----
        float pacc[2][4];
        #pragma unroll
        for (int mt = 0; mt < 2; ++mt)
            #pragma unroll
            for (int e = 0; e < 4; ++e) pacc[mt][e] = 0.f;
        #pragma unroll
        for (int term = 0; term < 2; ++term)
            #pragma unroll
            for (int kt = 0; kt < 2; ++kt)
                #pragma unroll
                for (int mt = 0; mt < 2; ++mt)
                    mma16816(pacc[mt], aF[mt][kt],
                             bW[term][kt][0], bW[term][kt][1]);

        char* sredBuf = smc + SM_SRED + (s & 1) * 2048;
        if ((lane & 3) == 0) {
            #pragma unroll
            for (int mt = 0; mt < 2; ++mt) {
                const int row = r00 + 16 * mt;
                *(float*)(sredBuf + (((row    ) * 2 + 0) * 4 + ng) * 4) = pacc[mt][0];
                *(float*)(sredBuf + (((row    ) * 2 + 1) * 4 + ng) * 4) = pacc[mt][1];
                *(float*)(sredBuf + (((row + 8) * 2 + 0) * 4 + ng) * 4) = pacc[mt][2];
                *(float*)(sredBuf + (((row + 8) * 2 + 1) * 4 + ng) * 4) = pacc[mt][3];
            }
        }
        __syncthreads();

        if (tid < 128) {
            const float4 v = *(const float4*)(sredBuf + tid * 16);
            float sum = (v.x + v.y) + (v.z + v.w);
            memout[tid] = fmaf(BETA, memout[tid], sum);
        }
    }

    // ---- epilogue ----
    if (tid < 128) {
        const int row = tid >> 1, o = tid & 1;
        const float v = o ? vy[0] : vx[0];
        out[((size_t)t * B_ + b0 + row) * 2 + o] = memout[tid] * v;
    }
}

// ---------------------------------------------------------------------------
extern "C" void kernel_launch(void* const* d_in, const int* in_sizes, int n_in,
                              void* d_out, int out_size) {
    const float* x    = (const float*)d_in[0];
    const float* Win  = (const float*)d_in[1];
    const float* Wh0  = (const float*)d_in[2];
    const float* Wout = (const float*)d_in[3];
    const float* vx   = (const float*)d_in[4];
    const float* vy   = (const float*)d_in[5];
    float* out = (float*)d_out;

    const int smem1 = (96 * 132 + 96 * 132) * 4;   // 101376 B
    const int smem2 = 129 * 128 * 4;               // 66048 B
    cudaFuncSetAttribute(k_gemm_in, cudaFuncAttributeMaxDynamicSharedMemorySize, smem1);
    cudaFuncSetAttribute(k_pl1,     cudaFuncAttributeMaxDynamicSharedMemorySize, smem2);
    cudaFuncSetAttribute(k_snn_b,   cudaFuncAttributeMaxDynamicSharedMemorySize, SM_TOTAL);

    k_gemm_in<<<(T_ * B_) / 128 + 1, 512, smem1>>>(x, Win, Wh0);
    k_pl1<<<BH / 128, 128, smem2>>>();
    k_snn_b<<<T_ * 16, 256, SM_TOTAL>>>(Wout, vx, vy, out);
}